// round 14
// baseline (speedup 1.0000x reference)
#include <cuda_runtime.h>
#include <cstdint>

#define NN 100000
#define EE 1600000
#define SPLIT 50048   // 64- and 8-aligned row split for the back-half pipeline

// ---------------- scratch (no allocations allowed) ----------------
__device__ float g_h1[(size_t)NN * 128];
__device__ float g_out1[(size_t)NN * 128];
__device__ float g_h2[(size_t)NN * 64];
__device__ float g_as1[NN];
__device__ float g_ad1[NN];
__device__ float g_as2[NN];
__device__ float g_ad2[NN];
__device__ int   g_deg[NN];
__device__ int   g_rowptr[NN + 1];
__device__ int   g_cursor[NN];
__device__ int   g_bsum[128];
__device__ int   g_colsrc[EE];
__device__ int   g_is64;
__device__ uint32_t g_wf1[16 * 16 * 32 * 4];   // W1 fragments (hi/lo tf32)
__device__ uint32_t g_wf2[16 * 8 * 32 * 4];    // W2 fragments

// ---------------- edge dtype sniff (warp-parallel) ----------------
// Node ids < 2^31: genuine int64 buffer has zero high words. 256 zero
// odd-words on real int32 data: P ~ (1e-5)^256 ~ 0.
__global__ void detect_edge_dtype(const int* __restrict__ ei32) {
    int ok = 1;
    for (int i = threadIdx.x; i < 256; i += 32)
        if (ei32[2 * i + 1] != 0) ok = 0;
    ok = __all_sync(0xffffffffu, ok);
    if (threadIdx.x == 0) g_is64 = ok;
}

__device__ __forceinline__ int load_edge(const void* ei, int i, int half) {
    int v;
    if (g_is64) v = (int)((const long long*)ei)[(size_t)half * EE + i];
    else        v = ((const int*)ei)[(size_t)half * EE + i];
    return min(max(v, 0), NN - 1);
}

__global__ __launch_bounds__(256) void histo_edges(const void* __restrict__ ei) {
    int i = blockIdx.x * 256 + threadIdx.x;
    if (i >= EE) return;
    atomicAdd(&g_deg[load_edge(ei, i, 1)], 1);
}

// ---------------- exclusive scan ----------------
__global__ __launch_bounds__(1024) void scan1() {
    __shared__ int sh[1024];
    int i = blockIdx.x * 1024 + threadIdx.x;
    int v = (i < NN) ? g_deg[i] : 0;
    sh[threadIdx.x] = v;
    __syncthreads();
    #pragma unroll
    for (int o = 1; o < 1024; o <<= 1) {
        int t = (threadIdx.x >= o) ? sh[threadIdx.x - o] : 0;
        __syncthreads();
        sh[threadIdx.x] += t;
        __syncthreads();
    }
    if (i < NN) g_rowptr[i] = sh[threadIdx.x] - v;
    if (threadIdx.x == 1023) g_bsum[blockIdx.x] = sh[1023];
}

__global__ void scan2(int nblk) {
    __shared__ int sh[128];
    int v = (threadIdx.x < nblk) ? g_bsum[threadIdx.x] : 0;
    sh[threadIdx.x] = v;
    __syncthreads();
    #pragma unroll
    for (int o = 1; o < 128; o <<= 1) {
        int t = (threadIdx.x >= o) ? sh[threadIdx.x - o] : 0;
        __syncthreads();
        sh[threadIdx.x] += t;
        __syncthreads();
    }
    if (threadIdx.x < nblk) g_bsum[threadIdx.x] = sh[threadIdx.x] - v;
}

__global__ __launch_bounds__(256) void scan3() {
    int i = blockIdx.x * 256 + threadIdx.x;
    if (i < NN) {
        int rp = g_rowptr[i] + g_bsum[i >> 10];
        g_rowptr[i] = rp;
        g_cursor[i] = rp;
    }
    if (i == NN) g_rowptr[NN] = EE;
}

__global__ __launch_bounds__(256) void fill_csr(const void* __restrict__ ei) {
    int e = blockIdx.x * 256 + threadIdx.x;
    if (e >= EE) return;
    int s = load_edge(ei, e, 0);
    int d = load_edge(ei, e, 1);
    int pos = atomicAdd(&g_cursor[d], 1);
    g_colsrc[pos] = s;
}

// ---------------- tf32 helpers ----------------
__device__ __forceinline__ uint32_t f2tf32(float x) {
    uint32_t r;
    asm("cvt.rna.tf32.f32 %0, %1;" : "=r"(r) : "f"(x));
    return r;
}
__device__ __forceinline__ uint32_t tf32lo(float x, uint32_t hi) {
    return f2tf32(x - __uint_as_float(hi));
}

#define MMA_TF32(d, a0, a1, a2, a3, b0, b1)                                \
    asm volatile("mma.sync.aligned.m16n8k8.row.col.f32.tf32.tf32.f32 "     \
        "{%0,%1,%2,%3}, {%4,%5,%6,%7}, {%8,%9}, {%0,%1,%2,%3};"            \
        : "+f"(d[0]), "+f"(d[1]), "+f"(d[2]), "+f"(d[3])                   \
        : "r"(a0), "r"(a1), "r"(a2), "r"(a3), "r"(b0), "r"(b1))

// ---------------- W fragment prep (once per layer) ----------------
__global__ __launch_bounds__(256) void prep_w(const float* __restrict__ W,
                                              uint32_t* __restrict__ wf,
                                              int N8) {
    int t = blockIdx.x * 256 + threadIdx.x;
    if (t >= 16 * N8 * 32) return;
    int lane = t & 31;
    int n8 = (t >> 5) % N8;
    int k8 = (t >> 5) / N8;
    int lr = lane >> 2, kq = lane & 3;
    int N = N8 * 8;
    float w0 = W[(size_t)(k8 * 8 + kq)     * N + n8 * 8 + lr];
    float w1 = W[(size_t)(k8 * 8 + kq + 4) * N + n8 * 8 + lr];
    uint32_t h0 = f2tf32(w0), h1 = f2tf32(w1);
    uint4 v = make_uint4(h0, h1, tf32lo(w0, h0), tf32lo(w1, h1));
    ((uint4*)wf)[t] = v;
}

// ---------------- tensor-core GEMM (3xTF32, K chunked) ------------------
// m0 = mbase + blockIdx*64 so the grid can cover a row sub-range.
// Logit outputs parameterized (as_out/ad_out) so layer2 doesn't clobber
// layer1 logits while the pipelined agg128-h1 still reads them.
template <int BN, bool RELU_BIAS>
__global__ __launch_bounds__(256) void gemm_tc(
    const float* __restrict__ X, const uint32_t* __restrict__ WF,
    const float* __restrict__ bin,
    const float* __restrict__ avs, const float* __restrict__ avd,
    float* __restrict__ H,
    float* __restrict__ as_out, float* __restrict__ ad_out,
    int mbase)
{
    constexpr int K = 128, BM = 64, KC = 64, KP = 68;  // 68 % 32 = 4: conflict-free
    constexpr int N8 = BN / 8;
    constexpr int NTW = BN / 32;
    constexpr int THREADS = 256;

    extern __shared__ float sm[];
    float* AsH = sm;                 // [BM][KP]
    float* AsL = sm + BM * KP;       // [BM][KP]

    const int tid = threadIdx.x, lane = tid & 31, wid = tid >> 5;
    const int wm = wid & 1, wn = wid >> 1;
    const int m0 = mbase + blockIdx.x * BM;
    const int lr = lane >> 2, kq = lane & 3;

    float acc[2][NTW][4];
    #pragma unroll
    for (int mt = 0; mt < 2; mt++)
        #pragma unroll
        for (int nt = 0; nt < NTW; nt++)
            #pragma unroll
            for (int c = 0; c < 4; c++) acc[mt][nt][c] = 0.f;

    const uint4* wf = (const uint4*)WF;

    #pragma unroll
    for (int kc = 0; kc < 2; kc++) {
        if (kc) __syncthreads();
        #pragma unroll
        for (int it = tid; it < BM * (KC / 4); it += THREADS) {
            int r = it >> 4, c4 = it & 15;
            float4 v = make_float4(0.f, 0.f, 0.f, 0.f);
            if (m0 + r < NN) {
                v = ((const float4*)X)[(size_t)(m0 + r) * (K / 4) + kc * (KC / 4) + c4];
                if constexpr (RELU_BIAS) {
                    float4 bb = ((const float4*)bin)[kc * (KC / 4) + c4];
                    v.x = fmaxf(v.x + bb.x, 0.f);
                    v.y = fmaxf(v.y + bb.y, 0.f);
                    v.z = fmaxf(v.z + bb.z, 0.f);
                    v.w = fmaxf(v.w + bb.w, 0.f);
                }
            }
            uint32_t hx = f2tf32(v.x), hy = f2tf32(v.y);
            uint32_t hz = f2tf32(v.z), hw = f2tf32(v.w);
            *(uint4*)&AsH[r * KP + c4 * 4] = make_uint4(hx, hy, hz, hw);
            *(uint4*)&AsL[r * KP + c4 * 4] =
                make_uint4(tf32lo(v.x, hx), tf32lo(v.y, hy),
                           tf32lo(v.z, hz), tf32lo(v.w, hw));
        }
        __syncthreads();

        #pragma unroll
        for (int k8 = 0; k8 < 8; k8++) {
            int k8g = kc * 8 + k8;
            int k0 = k8 * 8;
            uint4 bw[NTW];
            #pragma unroll
            for (int nt = 0; nt < NTW; nt++)
                bw[nt] = wf[(size_t)(k8g * N8 + wn * NTW + nt) * 32 + lane];

            uint32_t ah[2][4], al[2][4];
            #pragma unroll
            for (int mt = 0; mt < 2; mt++) {
                int base = (wm * 32 + mt * 16 + lr) * KP + k0 + kq;
                ah[mt][0] = *(const uint32_t*)&AsH[base];
                ah[mt][1] = *(const uint32_t*)&AsH[base + 8 * KP];
                ah[mt][2] = *(const uint32_t*)&AsH[base + 4];
                ah[mt][3] = *(const uint32_t*)&AsH[base + 8 * KP + 4];
                al[mt][0] = *(const uint32_t*)&AsL[base];
                al[mt][1] = *(const uint32_t*)&AsL[base + 8 * KP];
                al[mt][2] = *(const uint32_t*)&AsL[base + 4];
                al[mt][3] = *(const uint32_t*)&AsL[base + 8 * KP + 4];
            }
            #pragma unroll
            for (int nt = 0; nt < NTW; nt++)
                #pragma unroll
                for (int mt = 0; mt < 2; mt++)
                    MMA_TF32(acc[mt][nt], ah[mt][0], ah[mt][1], ah[mt][2], ah[mt][3], bw[nt].x, bw[nt].y);
            #pragma unroll
            for (int nt = 0; nt < NTW; nt++)
                #pragma unroll
                for (int mt = 0; mt < 2; mt++)
                    MMA_TF32(acc[mt][nt], al[mt][0], al[mt][1], al[mt][2], al[mt][3], bw[nt].x, bw[nt].y);
            #pragma unroll
            for (int nt = 0; nt < NTW; nt++)
                #pragma unroll
                for (int mt = 0; mt < 2; mt++)
                    MMA_TF32(acc[mt][nt], ah[mt][0], ah[mt][1], ah[mt][2], ah[mt][3], bw[nt].z, bw[nt].w);
        }
    }

    // ---- epilogue ----
    float sp[2][2], dp[2][2];
    #pragma unroll
    for (int mt = 0; mt < 2; mt++)
        sp[mt][0] = sp[mt][1] = dp[mt][0] = dp[mt][1] = 0.f;

    #pragma unroll
    for (int mt = 0; mt < 2; mt++) {
        int rA = m0 + wm * 32 + mt * 16 + lr;
        int rB = rA + 8;
        #pragma unroll
        for (int nt = 0; nt < NTW; nt++) {
            int c = (wn * NTW + nt) * 8 + kq * 2;
            float s0 = __ldg(&avs[c]), s1 = __ldg(&avs[c + 1]);
            float d0 = __ldg(&avd[c]), d1 = __ldg(&avd[c + 1]);
            sp[mt][0] += acc[mt][nt][0] * s0 + acc[mt][nt][1] * s1;
            dp[mt][0] += acc[mt][nt][0] * d0 + acc[mt][nt][1] * d1;
            sp[mt][1] += acc[mt][nt][2] * s0 + acc[mt][nt][3] * s1;
            dp[mt][1] += acc[mt][nt][2] * d0 + acc[mt][nt][3] * d1;
            if (rA < NN)
                *(float2*)&H[(size_t)rA * BN + c] = make_float2(acc[mt][nt][0], acc[mt][nt][1]);
            if (rB < NN)
                *(float2*)&H[(size_t)rB * BN + c] = make_float2(acc[mt][nt][2], acc[mt][nt][3]);
        }
    }
    #pragma unroll
    for (int o = 1; o <= 2; o <<= 1)
        #pragma unroll
        for (int mt = 0; mt < 2; mt++) {
            sp[mt][0] += __shfl_xor_sync(0xffffffffu, sp[mt][0], o);
            dp[mt][0] += __shfl_xor_sync(0xffffffffu, dp[mt][0], o);
            sp[mt][1] += __shfl_xor_sync(0xffffffffu, sp[mt][1], o);
            dp[mt][1] += __shfl_xor_sync(0xffffffffu, dp[mt][1], o);
        }

    __syncthreads();
    float* ep = sm;                  // smem reuse: ep[BM][4][2]
    if (kq == 0) {
        #pragma unroll
        for (int mt = 0; mt < 2; mt++) {
            int r0 = wm * 32 + mt * 16 + lr;
            ep[(r0 * 4 + wn) * 2 + 0]       = sp[mt][0];
            ep[(r0 * 4 + wn) * 2 + 1]       = dp[mt][0];
            ep[((r0 + 8) * 4 + wn) * 2 + 0] = sp[mt][1];
            ep[((r0 + 8) * 4 + wn) * 2 + 1] = dp[mt][1];
        }
    }
    __syncthreads();
    if (tid < BM && m0 + tid < NN) {
        float s = 0.f, d = 0.f;
        #pragma unroll
        for (int w = 0; w < 4; w++) {
            s += ep[(tid * 4 + w) * 2 + 0];
            d += ep[(tid * 4 + w) * 2 + 1];
        }
        as_out[m0 + tid] = s;
        ad_out[m0 + tid] = d;
    }
}

// ---------------- warp-per-row single-pass GAT aggregation ----------------
// rbase allows half-grids for the back-half pipeline.
template <int D, bool ADD_BIAS>
__global__ __launch_bounds__(256) void aggregate(
    const float* __restrict__ H, const float* __restrict__ bias,
    float* __restrict__ OUT,
    const float* __restrict__ asv, const float* __restrict__ adv,
    int rbase)
{
    constexpr int V = D / 32;
    int row = rbase + blockIdx.x * 8 + (threadIdx.x >> 5);
    if (row >= NN) return;
    int lane = threadIdx.x & 31;
    int beg = g_rowptr[row], end = g_rowptr[row + 1];
    float ad_r = adv[row];

    float den = 0.f;
    float acc[V];
    #pragma unroll
    for (int v = 0; v < V; v++) acc[v] = 0.f;

    for (int base = beg; base < end; base += 32) {
        int n = min(32, end - base);
        int s = 0; float ex = 0.f;
        if (lane < n) {
            s = __ldg(&g_colsrc[base + lane]);
            float e = __ldg(&asv[s]) + ad_r;
            e = e > 0.f ? e : 0.2f * e;
            ex = __expf(e);
            den += ex;
        }
        #pragma unroll 4
        for (int j = 0; j < n; j++) {
            int   sj = __shfl_sync(0xffffffffu, s, j);
            float wj = __shfl_sync(0xffffffffu, ex, j);
            const float* hp = H + (size_t)sj * D + lane * V;
            if constexpr (V == 4) {
                float4 h = __ldg((const float4*)hp);
                acc[0] = fmaf(wj, h.x, acc[0]);
                acc[1] = fmaf(wj, h.y, acc[1]);
                acc[2] = fmaf(wj, h.z, acc[2]);
                acc[3] = fmaf(wj, h.w, acc[3]);
            } else {
                float2 h = __ldg((const float2*)hp);
                acc[0] = fmaf(wj, h.x, acc[0]);
                acc[1] = fmaf(wj, h.y, acc[1]);
            }
        }
    }

    #pragma unroll
    for (int o = 16; o; o >>= 1) den += __shfl_xor_sync(0xffffffffu, den, o);
    float inv = 1.f / (den + 1e-16f);

    float* op = OUT + (size_t)row * D + lane * V;
    if constexpr (ADD_BIAS) {
        #pragma unroll
        for (int v = 0; v < V; v++) acc[v] = fmaf(acc[v], inv, bias[lane * V + v]);
    } else {
        #pragma unroll
        for (int v = 0; v < V; v++) acc[v] *= inv;
    }
    if constexpr (V == 4)
        *(float4*)op = make_float4(acc[0], acc[1], acc[2], acc[3]);
    else
        *(float2*)op = make_float2(acc[0], acc[1]);
}

// ---------------- launch (two-stream, pipelined back half) ---------------
extern "C" void kernel_launch(void* const* d_in, const int* in_sizes, int n_in,
                              void* d_out, int out_size) {
    const float* x   = (const float*)d_in[0];
    const void*  ei  = d_in[1];
    const float* W1  = (const float*)d_in[2];
    const float* as1 = (const float*)d_in[3];
    const float* ad1 = (const float*)d_in[4];
    const float* b1  = (const float*)d_in[5];
    const float* W2  = (const float*)d_in[6];
    const float* as2 = (const float*)d_in[7];
    const float* ad2 = (const float*)d_in[8];
    const float* b2  = (const float*)d_in[9];
    float* out = (float*)d_out;

    float *p_h1, *p_out1, *p_h2, *p_as1, *p_ad1, *p_as2, *p_ad2;
    int   *p_deg;
    uint32_t *p_wf1, *p_wf2;
    cudaGetSymbolAddress((void**)&p_h1,   g_h1);
    cudaGetSymbolAddress((void**)&p_out1, g_out1);
    cudaGetSymbolAddress((void**)&p_h2,   g_h2);
    cudaGetSymbolAddress((void**)&p_as1,  g_as1);
    cudaGetSymbolAddress((void**)&p_ad1,  g_ad1);
    cudaGetSymbolAddress((void**)&p_as2,  g_as2);
    cudaGetSymbolAddress((void**)&p_ad2,  g_ad2);
    cudaGetSymbolAddress((void**)&p_deg,  g_deg);
    cudaGetSymbolAddress((void**)&p_wf1,  g_wf1);
    cudaGetSymbolAddress((void**)&p_wf2,  g_wf2);

    const int SMEM = 2 * 64 * 68 * 4;   // 34,816 B
    cudaFuncSetAttribute(gemm_tc<128, false>,
                         cudaFuncAttributeMaxDynamicSharedMemorySize, SMEM);
    cudaFuncSetAttribute(gemm_tc<64, true>,
                         cudaFuncAttributeMaxDynamicSharedMemorySize, SMEM);

    const int nblk = (NN + 1023) / 1024;   // 98

    cudaStream_t sB;
    cudaStreamCreateWithFlags(&sB, cudaStreamNonBlocking);
    cudaEvent_t evFork, evJoin, evA0, evG0;
    cudaEventCreateWithFlags(&evFork, cudaEventDisableTiming);
    cudaEventCreateWithFlags(&evJoin, cudaEventDisableTiming);
    cudaEventCreateWithFlags(&evA0,   cudaEventDisableTiming);
    cudaEventCreateWithFlags(&evG0,   cudaEventDisableTiming);

    // origin: dtype sniff (needed by both branches)
    detect_edge_dtype<<<1, 32>>>((const int*)ei);
    cudaEventRecord(evFork, 0);
    cudaStreamWaitEvent(sB, evFork, 0);

    // stream B: prep_w2 + CSR build (all independent of gemm1 chain)
    prep_w<<<(16 * 8 * 32 + 255) / 256, 256, 0, sB>>>(W2, p_wf2, 8);
    cudaMemsetAsync(p_deg, 0, NN * sizeof(int), sB);
    histo_edges<<<(EE + 255) / 256, 256, 0, sB>>>(ei);
    scan1<<<nblk, 1024, 0, sB>>>();
    scan2<<<1, 128, 0, sB>>>(nblk);
    scan3<<<(NN + 256) / 256, 256, 0, sB>>>();
    fill_csr<<<(EE + 255) / 256, 256, 0, sB>>>(ei);
    cudaEventRecord(evJoin, sB);

    // origin: gemm1 (overlaps CSR build)
    prep_w<<<(16 * 16 * 32 + 255) / 256, 256>>>(W1, p_wf1, 16);
    gemm_tc<128, false><<<(NN + 63) / 64, 256, SMEM>>>(
        x, p_wf1, nullptr, as1, ad1, p_h1, p_as1, p_ad1, 0);

    // join CSR, then pipelined back half:
    //   agg128_h0 -> (gemm2_h0 on sB) || agg128_h1 -> gemm2_h1 -> agg64
    cudaStreamWaitEvent(0, evJoin, 0);
    aggregate<128, false><<<SPLIT / 8, 256>>>(
        p_h1, nullptr, p_out1, p_as1, p_ad1, 0);
    cudaEventRecord(evA0, 0);
    aggregate<128, false><<<(NN - SPLIT + 7) / 8, 256>>>(
        p_h1, nullptr, p_out1, p_as1, p_ad1, SPLIT);

    cudaStreamWaitEvent(sB, evA0, 0);
    gemm_tc<64, true><<<SPLIT / 64, 256, SMEM, sB>>>(
        p_out1, p_wf2, b1, as2, ad2, p_h2, p_as2, p_ad2, 0);
    cudaEventRecord(evG0, sB);

    gemm_tc<64, true><<<(NN - SPLIT + 63) / 64, 256, SMEM>>>(
        p_out1, p_wf2, b1, as2, ad2, p_h2, p_as2, p_ad2, SPLIT);

    cudaStreamWaitEvent(0, evG0, 0);
    aggregate<64, true><<<(NN + 7) / 8, 256>>>(
        p_h2, b2, out, p_as2, p_ad2, 0);

    cudaEventDestroy(evFork);
    cudaEventDestroy(evJoin);
    cudaEventDestroy(evA0);
    cudaEventDestroy(evG0);
    cudaStreamDestroy(sB);
}